// round 14
// baseline (speedup 1.0000x reference)
#include <cuda_runtime.h>
#include <math.h>

#define B 1024
#define D 64
#define O 64
#define M 1024
#define DELTA_F 0.13533528323661270f   // exp(-2)

// ------------------------- device scratch (no mallocs) -------------------------
__device__ float g_sen[B];          // ||x_i||^2
__device__ float g_gterm;           // gsm - sum(gm^2)
__device__ int   g_flag;            // 1 => fast-path hypothesis violated -> run scan
__device__ float g_protos[M * D];
__device__ float g_cents [M * D];
__device__ float g_senc[M];
__device__ float g_cc[M];           // sum(cents^2) per rule
__device__ float g_pp[M];           // sum(protos^2) per rule
__device__ int   g_sup[M];
__device__ int   g_n;
__device__ float g_Gt[B * M];       // fallback only: Gt[i*M + j] = dot(protos_j, x_i)

// ------------------------- K1: sen (per-thread row) + g_term + flag reset ------
__global__ void __launch_bounds__(1024) k_sengterm(const float* __restrict__ x) {
    __shared__ float part[16][64];
    __shared__ float red[32];
    __shared__ float gsq[64];
    int t = threadIdx.x;          // 1024 threads, 1 block
    // phase A: sen of row t (16 float4 loads, coalesced across warp)
    const float4* xv = reinterpret_cast<const float4*>(x) + t * 16;
    float s = 0.f;
    #pragma unroll
    for (int m = 0; m < 16; m++) {
        float4 v = xv[m];
        s += v.x * v.x + v.y * v.y + v.z * v.z + v.w * v.w;
    }
    g_sen[t] = s;
    // phase B: column sums (x is L2-hot after phase A)
    int d = t & 63, g = t >> 6;
    float cs = 0.f;
    for (int r = g; r < B; r += 16) cs += x[r * D + d];
    part[g][d] = cs;
    // phase C: sum of sen over all rows (warp shfl + smem)
    float ss = s;
    #pragma unroll
    for (int o = 16; o > 0; o >>= 1) ss += __shfl_down_sync(0xffffffffu, ss, o);
    if ((t & 31) == 0) red[t >> 5] = ss;
    __syncthreads();
    if (t < 32) {
        float v = red[t];
        #pragma unroll
        for (int o = 16; o > 0; o >>= 1) v += __shfl_down_sync(0xffffffffu, v, o);
        if (t == 0) red[0] = v;
    }
    __syncthreads();
    if (t < 64) {
        float c2 = 0.f;
        #pragma unroll
        for (int gg = 0; gg < 16; gg++) c2 += part[gg][t];
        float gm = c2 / (1048576.0f);         // (colsum/B)/B
        gsq[t] = gm * gm;
    }
    __syncthreads();
    if (t == 0) {
        float sq = 0.f;
        for (int dd = 0; dd < 64; dd++) sq += gsq[dd];
        float gsm = red[0] / 1048576.0f;      // (sensum/B)/B
        g_gterm = gsm - sq;
        g_flag = 0;
        g_n = B;
    }
}

// ------------------------- K2: all-pairs verification, FLAG ONLY ---------------
// 32x32 triangular tiles (528 blocks, ~3.5/SM), float4 XOR-swizzled SMEM.
// Condition for fast path: every off-diag pair has d2 > 64|g_term| = 128*stau.
//   * d2 > |g_term| = 2*stau  => reference scan creates a rule at every step
//     (stau_j = |g_term|/2 exactly in the all-create state: senc_j == cc_j bitwise)
//   * d2 > 128*stau => every off-diag reference dens has arg <= -128, and
//     expf(-128) ~ 2.6e-56 < min fp32 subnormal => dens is BITWISE 0.0f. The
//     reference lambda is then exactly the identity (dens_ii/dens_ii == 1.0f),
//     so the fast path may emit it bitwise-exactly.
__global__ void __launch_bounds__(256) k_verify(const float* __restrict__ x) {
    __shared__ float4 xi[32][16];
    __shared__ float4 xj[32][16];
    int rem = blockIdx.x, by = 0;
    while (rem >= 32 - by) { rem -= 32 - by; by++; }
    int bx = by + rem;
    int i0 = by * 32, j0 = bx * 32;
    int lt = threadIdx.x;
    int tx = lt & 15, ty = lt >> 4;
    const float4* xv = reinterpret_cast<const float4*>(x);
    #pragma unroll
    for (int k = 0; k < 2; k++) {
        int idx = lt + k * 256;
        int r = idx >> 4, c = idx & 15;
        xi[r][c ^ (r & 15)] = xv[(i0 + r) * 16 + c];
        xj[r][c ^ (r & 15)] = xv[(j0 + r) * 16 + c];
    }
    __syncthreads();
    float a00 = 0.f, a01 = 0.f, a10 = 0.f, a11 = 0.f;
    #pragma unroll
    for (int d4 = 0; d4 < 16; d4++) {
        float4 a0 = xi[ty][d4 ^ ty];
        float4 a1 = xi[ty + 16][d4 ^ ty];     // (ty+16)&15 == ty
        float4 b0 = xj[tx][d4 ^ tx];
        float4 b1 = xj[tx + 16][d4 ^ tx];
        a00 += a0.x * b0.x + a0.y * b0.y + a0.z * b0.z + a0.w * b0.w;
        a01 += a0.x * b1.x + a0.y * b1.y + a0.z * b1.z + a0.w * b1.w;
        a10 += a1.x * b0.x + a1.y * b0.y + a1.z * b0.z + a1.w * b0.w;
        a11 += a1.x * b1.x + a1.y * b1.y + a1.z * b1.z + a1.w * b1.w;
    }
    float thr = 64.0f * fabsf(g_gterm);
    int ia = i0 + ty, ib = i0 + ty + 16;
    int ja = j0 + tx, jb = j0 + tx + 16;
    float sia = g_sen[ia], sib = g_sen[ib];
    float sja = g_sen[ja], sjb = g_sen[jb];
    int bad = 0;
    bad |= (ia != ja) && (sia + sja - 2.0f * a00 < thr);
    bad |= (ia != jb) && (sia + sjb - 2.0f * a01 < thr);
    bad |= (ib != ja) && (sib + sja - 2.0f * a10 < thr);
    bad |= (ib != jb) && (sib + sjb - 2.0f * a11 < thr);
    if (__syncthreads_or(bad)) {
        if (lt == 0) atomicOr(&g_flag, 1);
    }
}

// ------------------------- K3: exact sequential scan (fallback, normally skipped) ---
__global__ void __launch_bounds__(1024, 1) k_scan_fallback(const float* __restrict__ x) {
    if (g_flag == 0) return;
    __shared__ float xs[64];
    __shared__ float red_val[32];
    __shared__ int   red_idx[32];
    __shared__ int s_n, s_w, s_create;
    __shared__ float s_sf;
    int t = threadIdx.x;
    if (t == 0) s_n = 0;
    __syncthreads();
    float gterm = g_gterm;
    for (int i = 0; i < B; i++) {
        if (t < 64) xs[t] = x[i * D + t];
        __syncthreads();
        int n = s_n;
        float dens;
        if (t < n) {
            float dist = 0.f;
            #pragma unroll 8
            for (int d = 0; d < 64; d++) { float v = xs[d] - g_protos[t * D + d]; dist += v * v; }
            float stau = fabsf(gterm + g_senc[t] - g_cc[t]) * 0.5f;
            dens = expf(-dist / stau);
        } else dens = -INFINITY;
        float v = dens; int idx = t;
        #pragma unroll
        for (int o = 16; o > 0; o >>= 1) {
            float ov = __shfl_down_sync(0xffffffffu, v, o);
            int   oi = __shfl_down_sync(0xffffffffu, idx, o);
            if (ov > v || (ov == v && oi < idx)) { v = ov; idx = oi; }
        }
        if ((t & 31) == 0) { red_val[t >> 5] = v; red_idx[t >> 5] = idx; }
        __syncthreads();
        if (t < 32) {
            v = red_val[t]; idx = red_idx[t];
            #pragma unroll
            for (int o = 16; o > 0; o >>= 1) {
                float ov = __shfl_down_sync(0xffffffffu, v, o);
                int   oi = __shfl_down_sync(0xffffffffu, idx, o);
                if (ov > v || (ov == v && oi < idx)) { v = ov; idx = oi; }
            }
            if (t == 0) {
                int create = (n == 0) || (v < DELTA_F);
                int w = create ? min(n, M - 1) : idx;
                int supn = create ? 1 : (g_sup[w] + 1);
                g_sup[w] = supn;
                s_w = w; s_create = create; s_sf = (float)supn;
                if (create) s_n = min(n + 1, M);
            }
        }
        __syncthreads();
        int w = s_w; float sf = s_sf; int create = s_create;
        if (t < 64) {
            float xiv = xs[t];
            float p = create ? 0.f : g_protos[w * D + t];
            float c = create ? 0.f : g_cents[w * D + t];
            g_protos[w * D + t] = create ? xiv : p;
            g_cents [w * D + t] = create ? xiv : (c + (xiv - c) / sf);
        }
        __syncthreads();
        if (t < 32) {
            float a = g_cents[w * D + t], b2 = g_cents[w * D + t + 32];
            float s = a * a + b2 * b2;
            #pragma unroll
            for (int o = 16; o > 0; o >>= 1) s += __shfl_down_sync(0xffffffffu, s, o);
            if (t == 0) {
                float si = g_sen[i];
                float sc = create ? 0.f : g_senc[w];
                g_senc[w] = create ? si : (sc + (si - sc) / sf);
                g_cc[w] = s;
            }
        }
        __syncthreads();
    }
    if (t == 0) g_n = s_n;
    __syncthreads();
    // recompute pp and Gt from final protos (slow; only on fallback)
    for (int j = t; j < M; j += 1024) {
        float s = 0.f;
        for (int d = 0; d < 64; d++) { float p = g_protos[j * D + d]; s += p * p; }
        g_pp[j] = s;
    }
    for (int k = t; k < B * M; k += 1024) {
        int i = k >> 10, j = k & (M - 1);
        float s = 0.f;
        for (int d = 0; d < 64; d++) s += g_protos[j * D + d] * x[i * D + d];
        g_Gt[k] = s;
    }
}

// ------------------------- K4: output (block per row i) -------------------------
// Fast path (flag==0): d_out pre-zeroed by memset; write ONLY the diagonal
// y_n block (16 float4) for this row.
// Fallback (flag==1): exact dens from scan state + Gt; write the full row.
__global__ void __launch_bounds__(256) k_out(const float* __restrict__ x,
                                             const float* __restrict__ W,
                                             const float* __restrict__ b,
                                             float4* __restrict__ out) {
    __shared__ float lam_s[1024];
    __shared__ float ynp[4][64];
    __shared__ __align__(16) float yn_f[64];
    __shared__ __align__(16) float xs[64];
    __shared__ float red[8];
    __shared__ float s_inv;
    int i = blockIdx.x, t = threadIdx.x;       // 256 threads
    if (t < 64) xs[t] = x[i * D + t];
    __syncthreads();
    int flag = g_flag;                          // block-uniform
    // --- y_n partials, balanced over all 256 threads (4 threads per output) ---
    {
        int o = t & 63, q = t >> 6;
        const float4* Wv = reinterpret_cast<const float4*>(W);
        const float4* xv4 = reinterpret_cast<const float4*>(xs);
        float z = 0.f;
        #pragma unroll
        for (int m = 0; m < 4; m++) {
            float4 w4 = Wv[o * 16 + q * 4 + m];
            float4 xx = xv4[q * 4 + m];
            z += w4.x * xx.x + w4.y * xx.y + w4.z * xx.z + w4.w * xx.w;
        }
        ynp[q][o] = z;
    }
    float dv[4];
    if (flag) {
        // --- exact dens over all j (fallback state) ---
        float sen_i = g_sen[i];
        float gterm = g_gterm;
        int n = g_n;
        float local = 0.f;
        #pragma unroll
        for (int k = 0; k < 4; k++) {
            int j = t + k * 256;
            float stau = fabsf(gterm + g_senc[j] - g_cc[j]) * 0.5f;
            float d2 = fmaxf(sen_i + g_pp[j] - 2.0f * g_Gt[i * M + j], 0.0f);
            float arg = -d2 / stau;
            float dens = 0.0f;
            if (j < n && arg > -85.0f) dens = expf(arg);
            dv[k] = dens;
            local += dens;
        }
        #pragma unroll
        for (int o = 16; o > 0; o >>= 1) local += __shfl_down_sync(0xffffffffu, local, o);
        if ((t & 31) == 0) red[t >> 5] = local;
    }
    __syncthreads();
    if (t >= 64 && t < 128) {
        int o = t - 64;
        float z = ynp[0][o] + ynp[1][o] + ynp[2][o] + ynp[3][o] + b[o];
        yn_f[o] = 1.0f / (1.0f + expf(-z));
    }
    if (flag && t < 8) {
        float v = red[t];
        #pragma unroll
        for (int o = 4; o > 0; o >>= 1) v += __shfl_down_sync(0xffu, v, o);
        if (t == 0) s_inv = 1.0f / v;
    }
    __syncthreads();
    if (!flag) {
        // lambda == identity, zeros already in place: write diagonal block only.
        if (t < 16) {
            float4 v = reinterpret_cast<const float4*>(yn_f)[t];
            __stcs(out + (size_t)i * 16384 + (i * 16 + t), v);
        }
        return;
    }
    // ---------------- fallback: full row write ----------------
    float inv = s_inv;
    #pragma unroll
    for (int k = 0; k < 4; k++) lam_s[t + k * 256] = dv[k] * inv;
    __syncthreads();
    const float4* yn4 = reinterpret_cast<const float4*>(yn_f);
    float4 base = yn4[t & 15];
    float4* dst = out + (size_t)i * 16384 + t;
    int r0 = t >> 4;
    #pragma unroll
    for (int k = 0; k < 64; k++) {
        float l = lam_s[r0 + 16 * k];
        float4 v;
        v.x = base.x * l; v.y = base.y * l; v.z = base.z * l; v.w = base.w * l;
        __stcs(dst + 256 * k, v);
    }
}

// ------------------------- launch -------------------------
extern "C" void kernel_launch(void* const* d_in, const int* in_sizes, int n_in,
                              void* d_out, int out_size) {
    const float* x = (const float*)d_in[0];
    const float* W = (const float*)d_in[1];
    const float* b = (const float*)d_in[2];
    float4* out = (float4*)d_out;

    // bulk zero-fill (graph-capturable async memset; no allocation).
    cudaMemsetAsync(d_out, 0, (size_t)B * M * O * sizeof(float));
    k_sengterm<<<1, 1024>>>(x);
    k_verify<<<528, 256>>>(x);
    k_scan_fallback<<<1, 1024>>>(x);
    k_out<<<B, 256>>>(x, W, b, out);
}

// round 15
// speedup vs baseline: 1.0512x; 1.0512x over previous
#include <cuda_runtime.h>
#include <math.h>

#define B 1024
#define D 64
#define O 64
#define M 1024
#define DELTA_F 0.13533528323661270f   // exp(-2)

// ------------------------- device scratch (no mallocs) -------------------------
__device__ float g_sen[B];          // ||x_i||^2
__device__ float g_gterm;           // gsm - sum(gm^2)
__device__ int   g_flag;            // 1 => fast-path hypothesis violated -> run scan
__device__ int   g_min_bits = 0x7f800000;  // +inf; min off-diag d^2 (int-compare of
                                           // non-negative floats). Consumed then reset
                                           // by k_gterm_scan each call => replays see
                                           // +inf again (first call: module-load init).
__device__ float g_protos[M * D];
__device__ float g_cents [M * D];
__device__ float g_senc[M];
__device__ float g_cc[M];           // sum(cents^2) per rule
__device__ float g_pp[M];           // sum(protos^2) per rule
__device__ int   g_sup[M];
__device__ int   g_n;
__device__ float g_Gt[B * M];       // fallback only: Gt[i*M + j] = dot(protos_j, x_i)

// ------------------------- K1: all-pairs min off-diag d^2 (NO dependencies) ----
// 32x32 triangular tiles (528 blocks), float4 XOR-swizzled SMEM. Row norms are
// computed from the block's own tiles, so this kernel depends only on x and can
// run first. Produces atomicMin(g_min_bits, min off-diag d^2).
// Fast-path condition (checked later): min d2 > 64|g_term| = 128*stau.
//   * d2 > |g_term| = 2*stau  => reference scan creates a rule at every step
//     (stau_j = |g_term|/2 exactly in the all-create state: senc_j == cc_j bitwise)
//   * d2 > 128*stau => every off-diag reference dens has arg <= -128, and
//     expf(-128) ~ 2.6e-56 < min fp32 subnormal => dens is BITWISE 0.0f. The
//     reference lambda is then exactly the identity (dens_ii/dens_ii == 1.0f),
//     so the fast path may emit it bitwise-exactly.
__global__ void __launch_bounds__(256) k_verify_min(const float* __restrict__ x) {
    __shared__ float4 xi[32][16];
    __shared__ float4 xj[32][16];
    __shared__ float sni[32], snj[32];
    int rem = blockIdx.x, by = 0;
    while (rem >= 32 - by) { rem -= 32 - by; by++; }
    int bx = by + rem;
    int i0 = by * 32, j0 = bx * 32;
    int lt = threadIdx.x;
    int tx = lt & 15, ty = lt >> 4;
    const float4* xv = reinterpret_cast<const float4*>(x);
    #pragma unroll
    for (int k = 0; k < 2; k++) {
        int idx = lt + k * 256;
        int r = idx >> 4, c = idx & 15;
        xi[r][c ^ (r & 15)] = xv[(i0 + r) * 16 + c];
        xj[r][c ^ (r & 15)] = xv[(j0 + r) * 16 + c];
    }
    __syncthreads();
    // row norms from the tiles (swizzle is a permutation; sum order irrelevant)
    if (lt < 32) {
        float s = 0.f;
        #pragma unroll
        for (int c = 0; c < 16; c++) { float4 v = xi[lt][c]; s += v.x*v.x + v.y*v.y + v.z*v.z + v.w*v.w; }
        sni[lt] = s;
    } else if (lt < 64) {
        int r = lt - 32;
        float s = 0.f;
        #pragma unroll
        for (int c = 0; c < 16; c++) { float4 v = xj[r][c]; s += v.x*v.x + v.y*v.y + v.z*v.z + v.w*v.w; }
        snj[r] = s;
    }
    __syncthreads();
    float a00 = 0.f, a01 = 0.f, a10 = 0.f, a11 = 0.f;
    #pragma unroll
    for (int d4 = 0; d4 < 16; d4++) {
        float4 a0 = xi[ty][d4 ^ ty];
        float4 a1 = xi[ty + 16][d4 ^ ty];     // (ty+16)&15 == ty
        float4 b0 = xj[tx][d4 ^ tx];
        float4 b1 = xj[tx + 16][d4 ^ tx];
        a00 += a0.x * b0.x + a0.y * b0.y + a0.z * b0.z + a0.w * b0.w;
        a01 += a0.x * b1.x + a0.y * b1.y + a0.z * b1.z + a0.w * b1.w;
        a10 += a1.x * b0.x + a1.y * b0.y + a1.z * b0.z + a1.w * b0.w;
        a11 += a1.x * b1.x + a1.y * b1.y + a1.z * b1.z + a1.w * b1.w;
    }
    int ia = i0 + ty, ib = i0 + ty + 16;
    int ja = j0 + tx, jb = j0 + tx + 16;
    float sia = sni[ty], sib = sni[ty + 16];
    float sja = snj[tx], sjb = snj[tx + 16];
    float m = 3.402823466e+38f;  // FLT_MAX
    if (ia != ja) m = fminf(m, sia + sja - 2.0f * a00);
    if (ia != jb) m = fminf(m, sia + sjb - 2.0f * a01);
    if (ib != ja) m = fminf(m, sib + sja - 2.0f * a10);
    if (ib != jb) m = fminf(m, sib + sjb - 2.0f * a11);
    m = fmaxf(m, 0.0f);          // keep int-compare monotonicity
    #pragma unroll
    for (int o = 16; o > 0; o >>= 1) m = fminf(m, __shfl_down_sync(0xffffffffu, m, o));
    if ((lt & 31) == 0) atomicMin(&g_min_bits, __float_as_int(m));
}

// ------------------------- K2: sen + g_term + flag decision + inline fallback scan ---
__global__ void __launch_bounds__(1024, 1) k_gterm_scan(const float* __restrict__ x) {
    __shared__ float part[16][64];
    __shared__ float red[32];
    __shared__ float gsq[64];
    __shared__ int s_flag;
    int t = threadIdx.x;          // 1024 threads, 1 block
    // phase A: sen of row t
    const float4* xv = reinterpret_cast<const float4*>(x) + t * 16;
    float s = 0.f;
    #pragma unroll
    for (int m = 0; m < 16; m++) {
        float4 v = xv[m];
        s += v.x * v.x + v.y * v.y + v.z * v.z + v.w * v.w;
    }
    g_sen[t] = s;
    // phase B: column sums
    int d = t & 63, g = t >> 6;
    float cs = 0.f;
    for (int r = g; r < B; r += 16) cs += x[r * D + d];
    part[g][d] = cs;
    // phase C: sum of sen
    float ss = s;
    #pragma unroll
    for (int o = 16; o > 0; o >>= 1) ss += __shfl_down_sync(0xffffffffu, ss, o);
    if ((t & 31) == 0) red[t >> 5] = ss;
    __syncthreads();
    if (t < 32) {
        float v = red[t];
        #pragma unroll
        for (int o = 16; o > 0; o >>= 1) v += __shfl_down_sync(0xffffffffu, v, o);
        if (t == 0) red[0] = v;
    }
    __syncthreads();
    if (t < 64) {
        float c2 = 0.f;
        #pragma unroll
        for (int gg = 0; gg < 16; gg++) c2 += part[gg][t];
        float gm = c2 / (1048576.0f);
        gsq[t] = gm * gm;
    }
    __syncthreads();
    if (t == 0) {
        float sq = 0.f;
        for (int dd = 0; dd < 64; dd++) sq += gsq[dd];
        float gsm = red[0] / 1048576.0f;
        float gterm = gsm - sq;
        g_gterm = gterm;
        float mind2 = __int_as_float(g_min_bits);
        int flag = (mind2 < 64.0f * fabsf(gterm)) ? 1 : 0;
        g_flag = flag;
        s_flag = flag;
        g_n = B;
        g_min_bits = 0x7f800000;   // reset for next graph replay
    }
    __syncthreads();
    if (s_flag == 0) return;
    // ---------------- exact sequential scan (fallback) ----------------
    __shared__ float xs[64];
    __shared__ float red_val[32];
    __shared__ int   red_idx[32];
    __shared__ int s_n, s_w, s_create;
    __shared__ float s_sf;
    if (t == 0) s_n = 0;
    __syncthreads();
    float gterm = g_gterm;
    for (int i = 0; i < B; i++) {
        if (t < 64) xs[t] = x[i * D + t];
        __syncthreads();
        int n = s_n;
        float dens;
        if (t < n) {
            float dist = 0.f;
            #pragma unroll 8
            for (int dd = 0; dd < 64; dd++) { float v = xs[dd] - g_protos[t * D + dd]; dist += v * v; }
            float stau = fabsf(gterm + g_senc[t] - g_cc[t]) * 0.5f;
            dens = expf(-dist / stau);
        } else dens = -INFINITY;
        float v = dens; int idx = t;
        #pragma unroll
        for (int o = 16; o > 0; o >>= 1) {
            float ov = __shfl_down_sync(0xffffffffu, v, o);
            int   oi = __shfl_down_sync(0xffffffffu, idx, o);
            if (ov > v || (ov == v && oi < idx)) { v = ov; idx = oi; }
        }
        if ((t & 31) == 0) { red_val[t >> 5] = v; red_idx[t >> 5] = idx; }
        __syncthreads();
        if (t < 32) {
            v = red_val[t]; idx = red_idx[t];
            #pragma unroll
            for (int o = 16; o > 0; o >>= 1) {
                float ov = __shfl_down_sync(0xffffffffu, v, o);
                int   oi = __shfl_down_sync(0xffffffffu, idx, o);
                if (ov > v || (ov == v && oi < idx)) { v = ov; idx = oi; }
            }
            if (t == 0) {
                int create = (n == 0) || (v < DELTA_F);
                int w = create ? min(n, M - 1) : idx;
                int supn = create ? 1 : (g_sup[w] + 1);
                g_sup[w] = supn;
                s_w = w; s_create = create; s_sf = (float)supn;
                if (create) s_n = min(n + 1, M);
            }
        }
        __syncthreads();
        int w = s_w; float sf = s_sf; int create = s_create;
        if (t < 64) {
            float xiv = xs[t];
            float p = create ? 0.f : g_protos[w * D + t];
            float c = create ? 0.f : g_cents[w * D + t];
            g_protos[w * D + t] = create ? xiv : p;
            g_cents [w * D + t] = create ? xiv : (c + (xiv - c) / sf);
        }
        __syncthreads();
        if (t < 32) {
            float a = g_cents[w * D + t], b2 = g_cents[w * D + t + 32];
            float s2 = a * a + b2 * b2;
            #pragma unroll
            for (int o = 16; o > 0; o >>= 1) s2 += __shfl_down_sync(0xffffffffu, s2, o);
            if (t == 0) {
                float si = g_sen[i];
                float sc = create ? 0.f : g_senc[w];
                g_senc[w] = create ? si : (sc + (si - sc) / sf);
                g_cc[w] = s2;
            }
        }
        __syncthreads();
    }
    if (t == 0) g_n = s_n;
    __syncthreads();
    // recompute pp and Gt from final protos (slow; only on fallback)
    for (int j = t; j < M; j += 1024) {
        float s2 = 0.f;
        for (int dd = 0; dd < 64; dd++) { float p = g_protos[j * D + dd]; s2 += p * p; }
        g_pp[j] = s2;
    }
    for (int k = t; k < B * M; k += 1024) {
        int i = k >> 10, j = k & (M - 1);
        float s2 = 0.f;
        for (int dd = 0; dd < 64; dd++) s2 += g_protos[j * D + dd] * x[i * D + dd];
        g_Gt[k] = s2;
    }
}

// ------------------------- K3: fused lambda + y_n + output (block per row i) ----
// Fast path (flag==0): lambda == identity bitwise -> y_n / zero stores from regs.
// Fallback (flag==1): exact dens from scan-produced state + Gt.
__global__ void __launch_bounds__(256) k_out(const float* __restrict__ x,
                                             const float* __restrict__ W,
                                             const float* __restrict__ b,
                                             float4* __restrict__ out) {
    __shared__ float lam_s[1024];
    __shared__ float ynp[4][64];
    __shared__ __align__(16) float yn_f[64];
    __shared__ __align__(16) float xs[64];
    __shared__ float red[8];
    __shared__ float s_inv;
    int i = blockIdx.x, t = threadIdx.x;       // 256 threads
    if (t < 64) xs[t] = x[i * D + t];
    __syncthreads();
    int flag = g_flag;                          // block-uniform
    // --- y_n partials, balanced over all 256 threads (4 threads per output) ---
    {
        int o = t & 63, q = t >> 6;
        const float4* Wv = reinterpret_cast<const float4*>(W);
        const float4* xv4 = reinterpret_cast<const float4*>(xs);
        float z = 0.f;
        #pragma unroll
        for (int m = 0; m < 4; m++) {
            float4 w4 = Wv[o * 16 + q * 4 + m];
            float4 xx = xv4[q * 4 + m];
            z += w4.x * xx.x + w4.y * xx.y + w4.z * xx.z + w4.w * xx.w;
        }
        ynp[q][o] = z;
    }
    float dv[4];
    if (flag) {
        // --- exact dens over all j (fallback state) ---
        float sen_i = g_sen[i];
        float gterm = g_gterm;
        int n = g_n;
        float local = 0.f;
        #pragma unroll
        for (int k = 0; k < 4; k++) {
            int j = t + k * 256;
            float stau = fabsf(gterm + g_senc[j] - g_cc[j]) * 0.5f;
            float d2 = fmaxf(sen_i + g_pp[j] - 2.0f * g_Gt[i * M + j], 0.0f);
            float arg = -d2 / stau;
            float dens = 0.0f;
            if (j < n && arg > -85.0f) dens = expf(arg);
            dv[k] = dens;
            local += dens;
        }
        #pragma unroll
        for (int o = 16; o > 0; o >>= 1) local += __shfl_down_sync(0xffffffffu, local, o);
        if ((t & 31) == 0) red[t >> 5] = local;
    }
    __syncthreads();
    if (t >= 64 && t < 128) {
        int o = t - 64;
        float z = ynp[0][o] + ynp[1][o] + ynp[2][o] + ynp[3][o] + b[o];
        yn_f[o] = 1.0f / (1.0f + expf(-z));
    }
    if (flag && t < 8) {
        float v = red[t];
        #pragma unroll
        for (int o = 4; o > 0; o >>= 1) v += __shfl_down_sync(0xffu, v, o);
        if (t == 0) s_inv = 1.0f / v;
    }
    __syncthreads();
    const float4* yn4 = reinterpret_cast<const float4*>(yn_f);
    float4 base = yn4[t & 15];
    float4* dst = out + (size_t)i * 16384 + t;
    int r0 = t >> 4;
    if (!flag) {
        // lambda == identity: rule-block i gets y_n, everything else zero
        float4 z4 = make_float4(0.f, 0.f, 0.f, 0.f);
        int hit = (r0 == (i & 15)) ? (i >> 4) : -1;
        #pragma unroll
        for (int k = 0; k < 64; k++) {
            float4 v = (k == hit) ? base : z4;
            __stcs(dst + 256 * k, v);        // streaming store: write-once data
        }
    } else {
        float inv = s_inv;
        #pragma unroll
        for (int k = 0; k < 4; k++) lam_s[t + k * 256] = dv[k] * inv;
        __syncthreads();
        #pragma unroll
        for (int k = 0; k < 64; k++) {
            float l = lam_s[r0 + 16 * k];
            float4 v;
            v.x = base.x * l; v.y = base.y * l; v.z = base.z * l; v.w = base.w * l;
            __stcs(dst + 256 * k, v);
        }
    }
}

// ------------------------- launch -------------------------
extern "C" void kernel_launch(void* const* d_in, const int* in_sizes, int n_in,
                              void* d_out, int out_size) {
    const float* x = (const float*)d_in[0];
    const float* W = (const float*)d_in[1];
    const float* b = (const float*)d_in[2];
    float4* out = (float4*)d_out;

    k_verify_min<<<528, 256>>>(x);
    k_gterm_scan<<<1, 1024>>>(x);
    k_out<<<B, 256>>>(x, W, b, out);
}

// round 16
// speedup vs baseline: 1.2140x; 1.1550x over previous
#include <cuda_runtime.h>
#include <math.h>

#define B 1024
#define D 64
#define O 64
#define M 1024
#define DELTA_F 0.13533528323661270f   // exp(-2)

// ------------------------- device scratch (no mallocs) -------------------------
__device__ float g_sen[B];          // ||x_i||^2
__device__ float g_gterm;           // gsm - sum(gm^2)
__device__ int   g_flag;            // 1 => fast-path hypothesis violated -> run scan
__device__ float g_protos[M * D];
__device__ float g_cents [M * D];
__device__ float g_senc[M];
__device__ float g_cc[M];           // sum(cents^2) per rule
__device__ float g_pp[M];           // sum(protos^2) per rule
__device__ int   g_sup[M];
__device__ int   g_n;
__device__ float g_Gt[B * M];       // fallback only: Gt[i*M + j] = dot(protos_j, x_i)

// ------------------------- K1: sen per row (warp per row) -------------------------
__global__ void k_sen(const float* __restrict__ x) {
    int warp = (blockIdx.x * blockDim.x + threadIdx.x) >> 5;
    int lane = threadIdx.x & 31;
    if (warp >= B) return;
    const float* row = x + warp * D;
    float a = row[lane], b = row[lane + 32];
    float s = a * a + b * b;
    #pragma unroll
    for (int o = 16; o > 0; o >>= 1) s += __shfl_down_sync(0xffffffffu, s, o);
    if (lane == 0) g_sen[warp] = s;
}

// ------------------------- K2: g_term, flag reset -------------------------
__global__ void k_gterm(const float* __restrict__ x) {
    __shared__ float part[16][64];
    __shared__ float red[32];
    __shared__ float gsq[64];
    int t = threadIdx.x;          // 1024 threads
    int d = t & 63, g = t >> 6;
    float s = 0.f;
    for (int r = g; r < B; r += 16) s += x[r * D + d];
    part[g][d] = s;

    float ss = g_sen[t];
    #pragma unroll
    for (int o = 16; o > 0; o >>= 1) ss += __shfl_down_sync(0xffffffffu, ss, o);
    if ((t & 31) == 0) red[t >> 5] = ss;
    __syncthreads();
    if (t < 32) {
        float v = red[t];
        #pragma unroll
        for (int o = 16; o > 0; o >>= 1) v += __shfl_down_sync(0xffffffffu, v, o);
        if (t == 0) red[0] = v;
    }
    __syncthreads();
    if (t < 64) {
        float cs = 0.f;
        #pragma unroll
        for (int gg = 0; gg < 16; gg++) cs += part[gg][t];
        float gm = cs / (1048576.0f);
        gsq[t] = gm * gm;
    }
    __syncthreads();
    if (t == 0) {
        float sq = 0.f;
        for (int dd = 0; dd < 64; dd++) sq += gsq[dd];
        float gsm = red[0] / 1048576.0f;
        g_gterm = gsm - sq;
        g_flag = 0;
        g_n = B;
    }
}

// ------------------------- K3: verification via 32-dim projection, FLAG ONLY ----
// For any coordinate subset S: d2_S(i,j) <= d2(i,j). We test the FIRST 32 coords:
// if every off-diag pair has d2_S > thr = 64|g_term| = 128*stau, then the full-dim
// condition holds a fortiori and the fast path is certified:
//   * d2 > |g_term| = 2*stau  => reference scan creates a rule at every step
//     (stau_j = |g_term|/2 exactly in the all-create state: senc_j == cc_j bitwise)
//   * d2 > 128*stau => every off-diag reference dens has arg <= -128, and
//     expf(-128) ~ 2.6e-56 < min fp32 subnormal => dens is BITWISE 0.0f. The
//     reference lambda is then exactly the identity (dens_ii/dens_ii == 1.0f),
//     so the fast path may emit it bitwise-exactly.
// A spurious flag (subspace pessimism) merely routes to the exact fallback.
__global__ void __launch_bounds__(256) k_verify(const float* __restrict__ x) {
    __shared__ float4 xi[32][8];    // first 32 floats of each row (8 float4)
    __shared__ float4 xj[32][8];
    __shared__ float sni[32], snj[32];   // 32-dim subspace norms
    int rem = blockIdx.x, by = 0;
    while (rem >= 32 - by) { rem -= 32 - by; by++; }
    int bx = by + rem;
    int i0 = by * 32, j0 = bx * 32;
    int lt = threadIdx.x;
    int tx = lt & 15, ty = lt >> 4;
    const float4* xv = reinterpret_cast<const float4*>(x);
    // load 32 rows x 8 float4 per side (256 float4 each); one float4 per thread
    {
        int r = lt >> 3, c = lt & 7;
        xi[r][c ^ (r & 7)] = xv[(i0 + r) * 16 + c];
        xj[r][c ^ (r & 7)] = xv[(j0 + r) * 16 + c];
    }
    __syncthreads();
    // subspace norms: threads 0..31 -> xi rows, 32..63 -> xj rows
    if (lt < 32) {
        float s = 0.f;
        #pragma unroll
        for (int c = 0; c < 8; c++) { float4 v = xi[lt][c]; s += v.x*v.x + v.y*v.y + v.z*v.z + v.w*v.w; }
        sni[lt] = s;
    } else if (lt < 64) {
        int r = lt - 32;
        float s = 0.f;
        #pragma unroll
        for (int c = 0; c < 8; c++) { float4 v = xj[r][c]; s += v.x*v.x + v.y*v.y + v.z*v.z + v.w*v.w; }
        snj[r] = s;
    }
    __syncthreads();
    float a00 = 0.f, a01 = 0.f, a10 = 0.f, a11 = 0.f;
    #pragma unroll
    for (int d4 = 0; d4 < 8; d4++) {
        float4 a0 = xi[ty][d4 ^ (ty & 7)];
        float4 a1 = xi[ty + 16][d4 ^ (ty & 7)];   // (ty+16)&7 == ty&7
        float4 b0 = xj[tx][d4 ^ (tx & 7)];
        float4 b1 = xj[tx + 16][d4 ^ (tx & 7)];
        a00 += a0.x * b0.x + a0.y * b0.y + a0.z * b0.z + a0.w * b0.w;
        a01 += a0.x * b1.x + a0.y * b1.y + a0.z * b1.z + a0.w * b1.w;
        a10 += a1.x * b0.x + a1.y * b0.y + a1.z * b0.z + a1.w * b0.w;
        a11 += a1.x * b1.x + a1.y * b1.y + a1.z * b1.z + a1.w * b1.w;
    }
    float thr = 64.0f * fabsf(g_gterm);
    int ia = i0 + ty, ib = i0 + ty + 16;
    int ja = j0 + tx, jb = j0 + tx + 16;
    float sia = sni[ty], sib = sni[ty + 16];
    float sja = snj[tx], sjb = snj[tx + 16];
    int bad = 0;
    bad |= (ia != ja) && (sia + sja - 2.0f * a00 < thr);
    bad |= (ia != jb) && (sia + sjb - 2.0f * a01 < thr);
    bad |= (ib != ja) && (sib + sja - 2.0f * a10 < thr);
    bad |= (ib != jb) && (sib + sjb - 2.0f * a11 < thr);
    if (__syncthreads_or(bad)) {
        if (lt == 0) atomicOr(&g_flag, 1);
    }
}

// ------------------------- K4: exact sequential scan (fallback, normally skipped) ---
__global__ void __launch_bounds__(1024, 1) k_scan_fallback(const float* __restrict__ x) {
    if (g_flag == 0) return;
    __shared__ float xs[64];
    __shared__ float red_val[32];
    __shared__ int   red_idx[32];
    __shared__ int s_n, s_w, s_create;
    __shared__ float s_sf;
    int t = threadIdx.x;
    if (t == 0) s_n = 0;
    __syncthreads();
    float gterm = g_gterm;
    for (int i = 0; i < B; i++) {
        if (t < 64) xs[t] = x[i * D + t];
        __syncthreads();
        int n = s_n;
        float dens;
        if (t < n) {
            float dist = 0.f;
            #pragma unroll 8
            for (int d = 0; d < 64; d++) { float v = xs[d] - g_protos[t * D + d]; dist += v * v; }
            float stau = fabsf(gterm + g_senc[t] - g_cc[t]) * 0.5f;
            dens = expf(-dist / stau);
        } else dens = -INFINITY;
        float v = dens; int idx = t;
        #pragma unroll
        for (int o = 16; o > 0; o >>= 1) {
            float ov = __shfl_down_sync(0xffffffffu, v, o);
            int   oi = __shfl_down_sync(0xffffffffu, idx, o);
            if (ov > v || (ov == v && oi < idx)) { v = ov; idx = oi; }
        }
        if ((t & 31) == 0) { red_val[t >> 5] = v; red_idx[t >> 5] = idx; }
        __syncthreads();
        if (t < 32) {
            v = red_val[t]; idx = red_idx[t];
            #pragma unroll
            for (int o = 16; o > 0; o >>= 1) {
                float ov = __shfl_down_sync(0xffffffffu, v, o);
                int   oi = __shfl_down_sync(0xffffffffu, idx, o);
                if (ov > v || (ov == v && oi < idx)) { v = ov; idx = oi; }
            }
            if (t == 0) {
                int create = (n == 0) || (v < DELTA_F);
                int w = create ? min(n, M - 1) : idx;
                int supn = create ? 1 : (g_sup[w] + 1);
                g_sup[w] = supn;
                s_w = w; s_create = create; s_sf = (float)supn;
                if (create) s_n = min(n + 1, M);
            }
        }
        __syncthreads();
        int w = s_w; float sf = s_sf; int create = s_create;
        if (t < 64) {
            float xiv = xs[t];
            float p = create ? 0.f : g_protos[w * D + t];
            float c = create ? 0.f : g_cents[w * D + t];
            g_protos[w * D + t] = create ? xiv : p;
            g_cents [w * D + t] = create ? xiv : (c + (xiv - c) / sf);
        }
        __syncthreads();
        if (t < 32) {
            float a = g_cents[w * D + t], b2 = g_cents[w * D + t + 32];
            float s = a * a + b2 * b2;
            #pragma unroll
            for (int o = 16; o > 0; o >>= 1) s += __shfl_down_sync(0xffffffffu, s, o);
            if (t == 0) {
                float si = g_sen[i];
                float sc = create ? 0.f : g_senc[w];
                g_senc[w] = create ? si : (sc + (si - sc) / sf);
                g_cc[w] = s;
            }
        }
        __syncthreads();
    }
    if (t == 0) g_n = s_n;
    __syncthreads();
    // recompute pp and Gt from final protos (slow; only on fallback)
    for (int j = t; j < M; j += 1024) {
        float s = 0.f;
        for (int d = 0; d < 64; d++) { float p = g_protos[j * D + d]; s += p * p; }
        g_pp[j] = s;
    }
    for (int k = t; k < B * M; k += 1024) {
        int i = k >> 10, j = k & (M - 1);
        float s = 0.f;
        for (int d = 0; d < 64; d++) s += g_protos[j * D + d] * x[i * D + d];
        g_Gt[k] = s;
    }
}

// ------------------------- K5: fused lambda + y_n + output (block per row i) ----
// Fast path (flag==0): lambda == identity bitwise -> y_n / zero stores from regs.
// Fallback (flag==1): exact dens from scan-produced state + Gt.
__global__ void __launch_bounds__(256) k_out(const float* __restrict__ x,
                                             const float* __restrict__ W,
                                             const float* __restrict__ b,
                                             float4* __restrict__ out) {
    __shared__ float lam_s[1024];
    __shared__ float ynp[4][64];
    __shared__ __align__(16) float yn_f[64];
    __shared__ __align__(16) float xs[64];
    __shared__ float red[8];
    __shared__ float s_inv;
    int i = blockIdx.x, t = threadIdx.x;       // 256 threads
    if (t < 64) xs[t] = x[i * D + t];
    __syncthreads();
    int flag = g_flag;                          // block-uniform
    // --- y_n partials, balanced over all 256 threads (4 threads per output) ---
    {
        int o = t & 63, q = t >> 6;
        const float4* Wv = reinterpret_cast<const float4*>(W);
        const float4* xv4 = reinterpret_cast<const float4*>(xs);
        float z = 0.f;
        #pragma unroll
        for (int m = 0; m < 4; m++) {
            float4 w4 = Wv[o * 16 + q * 4 + m];
            float4 xx = xv4[q * 4 + m];
            z += w4.x * xx.x + w4.y * xx.y + w4.z * xx.z + w4.w * xx.w;
        }
        ynp[q][o] = z;
    }
    float dv[4];
    if (flag) {
        // --- exact dens over all j (fallback state) ---
        float sen_i = g_sen[i];
        float gterm = g_gterm;
        int n = g_n;
        float local = 0.f;
        #pragma unroll
        for (int k = 0; k < 4; k++) {
            int j = t + k * 256;
            float stau = fabsf(gterm + g_senc[j] - g_cc[j]) * 0.5f;
            float d2 = fmaxf(sen_i + g_pp[j] - 2.0f * g_Gt[i * M + j], 0.0f);
            float arg = -d2 / stau;
            float dens = 0.0f;
            if (j < n && arg > -85.0f) dens = expf(arg);
            dv[k] = dens;
            local += dens;
        }
        #pragma unroll
        for (int o = 16; o > 0; o >>= 1) local += __shfl_down_sync(0xffffffffu, local, o);
        if ((t & 31) == 0) red[t >> 5] = local;
    }
    __syncthreads();
    if (t >= 64 && t < 128) {
        int o = t - 64;
        float z = ynp[0][o] + ynp[1][o] + ynp[2][o] + ynp[3][o] + b[o];
        yn_f[o] = 1.0f / (1.0f + expf(-z));
    }
    if (flag && t < 8) {
        float v = red[t];
        #pragma unroll
        for (int o = 4; o > 0; o >>= 1) v += __shfl_down_sync(0xffu, v, o);
        if (t == 0) s_inv = 1.0f / v;
    }
    __syncthreads();
    const float4* yn4 = reinterpret_cast<const float4*>(yn_f);
    float4 base = yn4[t & 15];
    float4* dst = out + (size_t)i * 16384 + t;
    int r0 = t >> 4;
    if (!flag) {
        // lambda == identity: rule-block i gets y_n, everything else zero
        float4 z4 = make_float4(0.f, 0.f, 0.f, 0.f);
        int hit = (r0 == (i & 15)) ? (i >> 4) : -1;
        #pragma unroll
        for (int k = 0; k < 64; k++) {
            float4 v = (k == hit) ? base : z4;
            __stcs(dst + 256 * k, v);        // streaming store: write-once data
        }
    } else {
        float inv = s_inv;
        #pragma unroll
        for (int k = 0; k < 4; k++) lam_s[t + k * 256] = dv[k] * inv;
        __syncthreads();
        #pragma unroll
        for (int k = 0; k < 64; k++) {
            float l = lam_s[r0 + 16 * k];
            float4 v;
            v.x = base.x * l; v.y = base.y * l; v.z = base.z * l; v.w = base.w * l;
            __stcs(dst + 256 * k, v);
        }
    }
}

// ------------------------- launch -------------------------
extern "C" void kernel_launch(void* const* d_in, const int* in_sizes, int n_in,
                              void* d_out, int out_size) {
    const float* x = (const float*)d_in[0];
    const float* W = (const float*)d_in[1];
    const float* b = (const float*)d_in[2];
    float4* out = (float4*)d_out;

    k_sen<<<B / 8, 256>>>(x);
    k_gterm<<<1, 1024>>>(x);
    k_verify<<<528, 256>>>(x);
    k_scan_fallback<<<1, 1024>>>(x);
    k_out<<<B, 256>>>(x, W, b, out);
}